// round 13
// baseline (speedup 1.0000x reference)
#include <cuda_runtime.h>
#include <cuda_fp16.h>
#include <cstdint>
#include <math.h>

#define NDIM 768
#define NTOK 512
#define BSZ 2
#define MALL 1024
#define NHEADS 12
#define DHEAD 64
#define DMLP 3072
#define NDEPTH 4
#define QKVW 2304
#define PATCHES 512
#define NBH (BSZ*NHEADS)

__device__ __forceinline__ uint32_t smem_u32(const void* p){
    uint32_t a;
    asm("{ .reg .u64 t; cvta.to.shared.u64 t, %1; cvt.u32.u64 %0, t; }" : "=r"(a) : "l"(p));
    return a;
}
#define CPA16(d, s) asm volatile("cp.async.cg.shared.global [%0], [%1], 16;" :: "r"(d), "l"(s))
#define CP_COMMIT() asm volatile("cp.async.commit_group;" ::: "memory")
#define CP_WAIT1()  asm volatile("cp.async.wait_group 1;" ::: "memory")
#define CP_WAIT0()  asm volatile("cp.async.wait_group 0;" ::: "memory")

__device__ __forceinline__ void ldm4(uint32_t addr, uint32_t* r){
    asm volatile("ldmatrix.sync.aligned.m8n8.x4.shared.b16 {%0,%1,%2,%3}, [%4];"
        : "=r"(r[0]), "=r"(r[1]), "=r"(r[2]), "=r"(r[3]) : "r"(addr));
}
__device__ __forceinline__ void mma16816(float* c, const uint32_t* a, const uint32_t* b){
    asm volatile("mma.sync.aligned.m16n8k16.row.col.f32.f16.f16.f32 "
        "{%0,%1,%2,%3}, {%4,%5,%6,%7}, {%8,%9}, {%0,%1,%2,%3};"
        : "+f"(c[0]), "+f"(c[1]), "+f"(c[2]), "+f"(c[3])
        : "r"(a[0]), "r"(a[1]), "r"(a[2]), "r"(a[3]), "r"(b[0]), "r"(b[1]));
}

// ---------------- scratch ----------------
__device__ __align__(256) __half g_pat[MALL*PATCHES];
__device__ __align__(256) __half g_cw[NDIM*PATCHES];
__device__ __align__(256) __half g_wqkvT[NDEPTH*QKVW*NDIM];
__device__ __align__(256) __half g_woT[NDEPTH*NDIM*NDIM];
__device__ __align__(256) __half g_w1T[NDEPTH*DMLP*NDIM];
__device__ __align__(256) __half g_w2T[NDEPTH*NDIM*DMLP];
__device__ __align__(256) float  g_x[MALL*NDIM];
__device__ __align__(256) __half g_h[MALL*NDIM];
__device__ __align__(256) __half g_qkv[MALL*QKVW];
__device__ __align__(256) float  g_scores[NBH*NTOK*NTOK];
__device__ __align__(256) __half g_p[NBH*NTOK*NTOK];
__device__ __align__(256) __half g_vt[NBH*DHEAD*NTOK];
__device__ __align__(256) __half g_o[MALL*NDIM];
__device__ __align__(256) __half g_m[MALL*DMLP];

// ---------------- prep kernels ----------------
__global__ void im2col_half(const float* __restrict__ vol, __half* __restrict__ o){
    int idx = blockIdx.x * 256 + threadIdx.x;
    int m = idx & 511, tkn = idx >> 9, n = tkn & 511, b = tkn >> 9;
    int k = m & 7, j = (m >> 3) & 7, i = m >> 6;
    int pw = n & 7, ph = (n >> 3) & 7, pd = n >> 6;
    o[idx] = __float2half_rn(vol[((long)b << 18) + (pd*8+i)*4096 + (ph*8+j)*64 + (pw*8+k)]);
}
__global__ void conv_half(const float* __restrict__ in, __half* __restrict__ o, int n){
    int idx = blockIdx.x * 256 + threadIdx.x;
    if (idx >= n) return;
    o[idx] = __float2half_rn(in[idx]);
}
// transpose+convert: fp32 [L][R][C] -> fp16 [L][C][R], 64R x 32C tiles
__global__ void wt_half(const float* __restrict__ in, __half* __restrict__ o, int R, int C){
    __shared__ float tf[64][33];
    int z = blockIdx.z;
    const float* ip = in + (long)z * R * C;
    int r0 = blockIdx.y * 64, c0 = blockIdx.x * 32;
    int tx = threadIdx.x, ty = threadIdx.y;   // 32 x 8
#pragma unroll
    for (int i = 0; i < 8; i++)
        tf[ty + 8*i][tx] = ip[(long)(r0 + ty + 8*i) * C + c0 + tx];
    __syncthreads();
    long ob = (long)z * R * C;
#pragma unroll
    for (int i = 0; i < 4; i++) {
        int c = ty + 8*i;
        int r = tx * 2;
        __half2 v = __halves2half2(__float2half_rn(tf[r][c]),
                                   __float2half_rn(tf[r+1][c]));
        *reinterpret_cast<__half2*>(&o[ob + (long)(c0 + c) * R + r0 + r]) = v;
    }
}

// ---------------- LN: single-pass, fp16 or fp32 out ----------------
template <int HALF>
__global__ void ln_kernel(const float* __restrict__ x, const float* __restrict__ w,
                          const float* __restrict__ bb, float* __restrict__ of,
                          __half* __restrict__ oh){
    __shared__ float red1[8], red2[8];
    const int row = blockIdx.x, t = threadIdx.x;
    const float* xp = x + (long)row * NDIM;
    float v0 = xp[t], v1 = xp[t+256], v2 = xp[t+512];
    float s1 = v0 + v1 + v2;
    float s2 = v0*v0 + v1*v1 + v2*v2;
#pragma unroll
    for (int o = 16; o; o >>= 1) {
        s1 += __shfl_xor_sync(~0u, s1, o);
        s2 += __shfl_xor_sync(~0u, s2, o);
    }
    if ((t & 31) == 0) { red1[t >> 5] = s1; red2[t >> 5] = s2; }
    __syncthreads();
    if (t < 32) {
        float r1 = (t < 8) ? red1[t] : 0.0f;
        float r2 = (t < 8) ? red2[t] : 0.0f;
#pragma unroll
        for (int o = 4; o; o >>= 1) {
            r1 += __shfl_xor_sync(~0u, r1, o);
            r2 += __shfl_xor_sync(~0u, r2, o);
        }
        if (t == 0) { red1[0] = r1; red2[0] = r2; }
    }
    __syncthreads();
    float mean = red1[0] * (1.0f / NDIM);
    float var  = red2[0] * (1.0f / NDIM) - mean * mean;
    float rs = rsqrtf(var + 1e-5f);
    float y0 = (v0-mean)*rs*w[t]     + bb[t];
    float y1 = (v1-mean)*rs*w[t+256] + bb[t+256];
    float y2 = (v2-mean)*rs*w[t+512] + bb[t+512];
    long o0 = (long)row * NDIM;
    if (HALF) {
        oh[o0+t]     = __float2half_rn(y0);
        oh[o0+t+256] = __float2half_rn(y1);
        oh[o0+t+512] = __float2half_rn(y2);
    } else {
        of[o0+t]=y0; of[o0+t+256]=y1; of[o0+t+512]=y2;
    }
}

// ---------------- softmax (fp32 scores -> fp16 P) ----------------
__global__ void softmax_half(const float* __restrict__ sc, __half* __restrict__ ph){
    __shared__ float redm[4], reds[4];
    long rb = (long)blockIdx.x * NTOK;
    const int t = threadIdx.x;
    float4 v = *reinterpret_cast<const float4*>(&sc[rb + t*4]);
    float m = fmaxf(fmaxf(v.x, v.y), fmaxf(v.z, v.w));
#pragma unroll
    for (int o = 16; o; o >>= 1) m = fmaxf(m, __shfl_xor_sync(~0u, m, o));
    if ((t & 31) == 0) redm[t >> 5] = m;
    __syncthreads();
    m = fmaxf(fmaxf(redm[0], redm[1]), fmaxf(redm[2], redm[3]));
    v.x = __expf(v.x-m); v.y = __expf(v.y-m); v.z = __expf(v.z-m); v.w = __expf(v.w-m);
    float s = v.x + v.y + v.z + v.w;
#pragma unroll
    for (int o = 16; o; o >>= 1) s += __shfl_xor_sync(~0u, s, o);
    if ((t & 31) == 0) reds[t >> 5] = s;
    __syncthreads();
    s = reds[0] + reds[1] + reds[2] + reds[3];
    float inv = 1.0f / s;
    long off = rb + t*4;
    reinterpret_cast<__half2*>(ph+off)[0] =
        __halves2half2(__float2half_rn(v.x*inv), __float2half_rn(v.y*inv));
    reinterpret_cast<__half2*>(ph+off)[1] =
        __halves2half2(__float2half_rn(v.z*inv), __float2half_rn(v.w*inv));
}

// ---------------- pure-fp16 GEMM via mma.sync ----------------
// C[M,N] = A[M,K] @ B[N,K]^T. 3-stage cp.async ring.
// EPI: 0 fp32*scale | 1 fp32 residual+=acc+bias | 2 tanh(acc+bias)->fp16
//      3 acc+bias+pos->fp32 | 4 acc->fp16 | 5 qkv fused (Q,K rows; V->vt transposed)
template <int BM, int BN>
__device__ __forceinline__ void ld_stage(uint32_t sb, int tid,
    const __half* pA, const __half* pB,
    long long lda, long long ldb, int row0, int col0, int k0){
    constexpr int ASZ = BM*80;
#pragma unroll
    for (int i = 0; i < BM/64; i++) {
        int ch = tid + i*256;
        int r = ch >> 2, c = ch & 3;
        uint32_t so = r*80 + c*16;
        CPA16(sb + so, pA + (long long)(row0 + r) * lda + k0 + c*8);
    }
#pragma unroll
    for (int i = 0; i < BN/64; i++) {
        int ch = tid + i*256;
        int r = ch >> 2, c = ch & 3;
        uint32_t so = r*80 + c*16;
        CPA16(sb + ASZ + so, pB + (long long)(col0 + r) * ldb + k0 + c*8);
    }
}

template <int BM, int BN, int EPI, int OCC>
__global__ void __launch_bounds__(256, OCC) mma_gemm(
    const __half* __restrict__ A, long long lda, long long aSB, long long aSH,
    const __half* __restrict__ B, long long ldb, long long bSB, long long bSH,
    float* __restrict__ Cf, __half* __restrict__ Oh, __half* __restrict__ Vt,
    long long ldc, long long cSB, long long cSH,
    const float* __restrict__ bias, const float* __restrict__ pos,
    float scale, int K, int heads)
{
    extern __shared__ __align__(128) char smem_raw[];
    uint32_t sb = smem_u32(smem_raw);
    constexpr int ASZ = BM*80;
    constexpr int BUF = (BM+BN)*80;
    constexpr int MW = BM/32;
    constexpr int NW = 8/MW;
    constexpr int WN = BN/NW;
    constexpr int NP = WN/16;
    constexpr int NT = WN/8;

    const int tid = threadIdx.x, lane = tid & 31, warp = tid >> 5;
    const int warpM = warp % MW, warpN = warp / MW;
    const int z = blockIdx.z, zb = z / heads, zh = z % heads;
    const __half* pA = A + zb*aSB + zh*aSH;
    const __half* pB = B + zb*bSB + zh*bSH;
    const long long cOff = zb*cSB + zh*cSH;
    const int row0 = blockIdx.y * BM, col0 = blockIdx.x * BN;

    float acc[2][NT][4];
#pragma unroll
    for (int a = 0; a < 2; a++)
#pragma unroll
        for (int b = 0; b < NT; b++)
#pragma unroll
            for (int c = 0; c < 4; c++) acc[a][b][c] = 0.0f;

    const int nst = K >> 5;
    ld_stage<BM,BN>(sb, tid, pA, pB, lda, ldb, row0, col0, 0);
    CP_COMMIT();
    if (nst > 1) {
        ld_stage<BM,BN>(sb + BUF, tid, pA, pB, lda, ldb, row0, col0, 32);
        CP_COMMIT();
    }

    const int L = lane & 7, jj = lane >> 3;
    for (int st = 0; st < nst; st++) {
        if (st < nst - 1) CP_WAIT1(); else CP_WAIT0();
        __syncthreads();
        if (st + 2 < nst) {
            ld_stage<BM,BN>(sb + ((st+2)%3)*BUF, tid, pA, pB,
                            lda, ldb, row0, col0, (st+2)*32);
            CP_COMMIT();
        }
        uint32_t base = sb + (st % 3) * BUF;
#pragma unroll
        for (int ks = 0; ks < 2; ks++) {
            uint32_t a_[2][4];
#pragma unroll
            for (int mi = 0; mi < 2; mi++) {
                int mrow = warpM*32 + mi*16 + (jj & 1)*8 + L;
                int kcol = ks*16 + (jj >> 1)*8;
                ldm4(base + mrow*80 + kcol*2, a_[mi]);
            }
            uint32_t b_[NP][4];
#pragma unroll
            for (int np = 0; np < NP; np++) {
                int nrow = warpN*WN + np*16 + (jj >> 1)*8 + L;
                int kcol = ks*16 + (jj & 1)*8;
                ldm4(base + ASZ + nrow*80 + kcol*2, b_[np]);
            }
#pragma unroll
            for (int mi = 0; mi < 2; mi++)
#pragma unroll
                for (int np = 0; np < NP; np++)
#pragma unroll
                    for (int si = 0; si < 2; si++) {
                        uint32_t f[2] = { b_[np][si*2], b_[np][si*2+1] };
                        mma16816(acc[mi][np*2 + si], a_[mi], f);
                    }
        }
    }

#pragma unroll
    for (int mi = 0; mi < 2; mi++)
#pragma unroll
        for (int nt = 0; nt < NT; nt++) {
            float* c = acc[mi][nt];
            int col = col0 + warpN*WN + nt*8 + (lane & 3)*2;
#pragma unroll
            for (int hf = 0; hf < 2; hf++) {
                int row = row0 + warpM*32 + mi*16 + (lane >> 2) + hf*8;
                float v0 = c[hf*2 + 0], v1 = c[hf*2 + 1];
                if (EPI == 0) {
                    float2* cp = reinterpret_cast<float2*>(Cf + cOff + (long long)row*ldc + col);
                    *cp = make_float2(v0*scale, v1*scale);
                } else if (EPI == 1) {
                    float2* cp = reinterpret_cast<float2*>(Cf + cOff + (long long)row*ldc + col);
                    float2 old = *cp;
                    *cp = make_float2(old.x + v0 + bias[col], old.y + v1 + bias[col+1]);
                } else if (EPI == 3) {
                    const float2* pp = reinterpret_cast<const float2*>(
                        pos + (long long)(row & (NTOK-1))*ldc + col);
                    float2 pv = *pp;
                    float2* cp = reinterpret_cast<float2*>(Cf + (long long)row*ldc + col);
                    *cp = make_float2(v0 + bias[col] + pv.x, v1 + bias[col+1] + pv.y);
                } else if (EPI == 5) {
                    if (col0 < 2*NDIM) {
                        long long off = (long long)row*ldc + col;
                        *reinterpret_cast<__half2*>(Oh + off) =
                            __halves2half2(__float2half_rn(v0), __float2half_rn(v1));
                    } else {
                        int bb2 = row >> 9, t2 = row & (NTOK-1);
                        int hd = col - 2*NDIM, hh2 = hd >> 6, d = hd & (DHEAD-1);
                        long vtb = ((long)(bb2*NHEADS + hh2)*DHEAD + d)*NTOK + t2;
                        Vt[vtb] = __float2half_rn(v0);
                        Vt[vtb + NTOK] = __float2half_rn(v1);
                    }
                } else {
                    if (EPI == 2) {
                        v0 = tanhf(v0 + bias[col]);
                        v1 = tanhf(v1 + bias[col+1]);
                    }
                    long long off = cOff + (long long)row*ldc + col;
                    *reinterpret_cast<__half2*>(Oh + off) =
                        __halves2half2(__float2half_rn(v0), __float2half_rn(v1));
                }
            }
        }
}

// ---------------- host ----------------
extern "C" void kernel_launch(void* const* d_in, const int* in_sizes, int n_in,
                              void* d_out, int out_size)
{
    const float* volume    = (const float*)d_in[0];
    const float* conv_w    = (const float*)d_in[1];
    const float* conv_b    = (const float*)d_in[2];
    const float* pos_embed = (const float*)d_in[3];
    const float* ln1_w     = (const float*)d_in[4];
    const float* ln1_b     = (const float*)d_in[5];
    const float* w_qkv     = (const float*)d_in[6];
    const float* w_o       = (const float*)d_in[7];
    const float* b_o       = (const float*)d_in[8];
    const float* ln2_w     = (const float*)d_in[9];
    const float* ln2_b     = (const float*)d_in[10];
    const float* w1        = (const float*)d_in[11];
    const float* b1        = (const float*)d_in[12];
    const float* w2        = (const float*)d_in[13];
    const float* b2        = (const float*)d_in[14];
    const float* lnf_w     = (const float*)d_in[15];
    const float* lnf_b     = (const float*)d_in[16];
    float* out = (float*)d_out;

    __half *pat,*cw,*wqT,*woT,*w1T,*w2T,*h,*qkv,*p,*vt,*o,*m;
    float *x, *scores;
    cudaGetSymbolAddress((void**)&pat, g_pat);
    cudaGetSymbolAddress((void**)&cw, g_cw);
    cudaGetSymbolAddress((void**)&wqT, g_wqkvT);
    cudaGetSymbolAddress((void**)&woT, g_woT);
    cudaGetSymbolAddress((void**)&w1T, g_w1T);
    cudaGetSymbolAddress((void**)&w2T, g_w2T);
    cudaGetSymbolAddress((void**)&x, g_x);
    cudaGetSymbolAddress((void**)&h, g_h);
    cudaGetSymbolAddress((void**)&qkv, g_qkv);
    cudaGetSymbolAddress((void**)&scores, g_scores);
    cudaGetSymbolAddress((void**)&p, g_p);
    cudaGetSymbolAddress((void**)&vt, g_vt);
    cudaGetSymbolAddress((void**)&o, g_o);
    cudaGetSymbolAddress((void**)&m, g_m);

    const int S_128_128 = 3*(128+128)*80;   // 61440
    const int S_128_192 = 3*(128+192)*80;   // 76800
    const int S_64_128  = 3*(64+128)*80;    // 46080
    const int S_128_64  = 3*(128+64)*80;    // 46080
    cudaFuncSetAttribute((const void*)mma_gemm<128,128,5,2>, cudaFuncAttributeMaxDynamicSharedMemorySize, S_128_128);
    cudaFuncSetAttribute((const void*)mma_gemm<128,128,0,2>, cudaFuncAttributeMaxDynamicSharedMemorySize, S_128_128);
    cudaFuncSetAttribute((const void*)mma_gemm<128,64,4,2>,  cudaFuncAttributeMaxDynamicSharedMemorySize, S_128_64);
    cudaFuncSetAttribute((const void*)mma_gemm<64,128,1,2>,  cudaFuncAttributeMaxDynamicSharedMemorySize, S_64_128);
    cudaFuncSetAttribute((const void*)mma_gemm<64,128,3,2>,  cudaFuncAttributeMaxDynamicSharedMemorySize, S_64_128);
    cudaFuncSetAttribute((const void*)mma_gemm<128,192,2,2>, cudaFuncAttributeMaxDynamicSharedMemorySize, S_128_192);

    dim3 tb(32, 8);

    im2col_half<<<(MALL*PATCHES)/256, 256>>>(volume, pat);
    conv_half<<<(NDIM*PATCHES)/256, 256>>>(conv_w, cw, NDIM*PATCHES);
    wt_half<<<dim3(QKVW/32, NDIM/64, NDEPTH), tb>>>(w_qkv, wqT, NDIM, QKVW);
    wt_half<<<dim3(NDIM/32, NDIM/64, NDEPTH), tb>>>(w_o, woT, NDIM, NDIM);
    wt_half<<<dim3(DMLP/32, NDIM/64, NDEPTH), tb>>>(w1, w1T, NDIM, DMLP);
    wt_half<<<dim3(NDIM/32, DMLP/64, NDEPTH), tb>>>(w2, w2T, DMLP, NDIM);

    // patch embed: x = patches @ conv_w^T + conv_b + pos  (64x128 tiles)
    mma_gemm<64,128,3,2><<<dim3(NDIM/128, MALL/64, 1), 256, S_64_128>>>(
        pat, PATCHES, 0, 0, cw, PATCHES, 0, 0,
        x, nullptr, nullptr, NDIM, 0, 0, conv_b, pos_embed, 1.f, PATCHES, 1);

    for (int l = 0; l < NDEPTH; ++l) {
        ln_kernel<1><<<MALL, 256>>>(x, ln1_w + l*NDIM, ln1_b + l*NDIM, nullptr, h);
        // QKV fused: Q,K rows stored; V transposed into vt
        mma_gemm<128,128,5,2><<<dim3(QKVW/128, MALL/128, 1), 256, S_128_128>>>(
            h, NDIM, 0, 0, wqT + (long)l*QKVW*NDIM, NDIM, 0, 0,
            nullptr, qkv, vt, QKVW, 0, 0, nullptr, nullptr, 1.f, NDIM, 1);
        // QK
        mma_gemm<128,128,0,2><<<dim3(NTOK/128, NTOK/128, NBH), 256, S_128_128>>>(
            qkv, QKVW, (long long)NTOK*QKVW, DHEAD,
            qkv + NDIM, QKVW, (long long)NTOK*QKVW, DHEAD,
            scores, nullptr, nullptr, NTOK, (long long)NHEADS*NTOK*NTOK, (long long)NTOK*NTOK,
            nullptr, nullptr, 0.125f, DHEAD, NHEADS);
        softmax_half<<<NBH*NTOK, 128>>>(scores, p);
        // PV (128x64 tiles)
        mma_gemm<128,64,4,2><<<dim3(1, NTOK/128, NBH), 256, S_128_64>>>(
            p, NTOK, (long long)NHEADS*NTOK*NTOK, (long long)NTOK*NTOK,
            vt, NTOK, (long long)NHEADS*DHEAD*NTOK, (long long)DHEAD*NTOK,
            nullptr, o, nullptr, NDIM, (long long)NTOK*NDIM, DHEAD,
            nullptr, nullptr, 1.f, NTOK, NHEADS);
        // O-proj (64x128 tiles)
        mma_gemm<64,128,1,2><<<dim3(NDIM/128, MALL/64, 1), 256, S_64_128>>>(
            o, NDIM, 0, 0, woT + (long)l*NDIM*NDIM, NDIM, 0, 0,
            x, nullptr, nullptr, NDIM, 0, 0, b_o + l*NDIM, nullptr, 1.f, NDIM, 1);
        ln_kernel<1><<<MALL, 256>>>(x, ln2_w + l*NDIM, ln2_b + l*NDIM, nullptr, h);
        mma_gemm<128,192,2,2><<<dim3(DMLP/192, MALL/128, 1), 256, S_128_192>>>(
            h, NDIM, 0, 0, w1T + (long)l*DMLP*NDIM, NDIM, 0, 0,
            nullptr, m, nullptr, DMLP, 0, 0, b1 + l*DMLP, nullptr, 1.f, NDIM, 1);
        // MLP2 (64x128 tiles)
        mma_gemm<64,128,1,2><<<dim3(NDIM/128, MALL/64, 1), 256, S_64_128>>>(
            m, DMLP, 0, 0, w2T + (long)l*NDIM*DMLP, DMLP, 0, 0,
            x, nullptr, nullptr, NDIM, 0, 0, b2 + l*NDIM, nullptr, 1.f, DMLP, 1);
    }

    ln_kernel<0><<<MALL, 256>>>(x, lnf_w, lnf_b, out, nullptr);
}

// round 14
// speedup vs baseline: 1.0390x; 1.0390x over previous
#include <cuda_runtime.h>
#include <cuda_fp16.h>
#include <cstdint>
#include <math.h>

#define NDIM 768
#define NTOK 512
#define BSZ 2
#define MALL 1024
#define NHEADS 12
#define DHEAD 64
#define DMLP 3072
#define NDEPTH 4
#define QKVW 2304
#define PATCHES 512
#define NBH (BSZ*NHEADS)

__device__ __forceinline__ uint32_t smem_u32(const void* p){
    uint32_t a;
    asm("{ .reg .u64 t; cvta.to.shared.u64 t, %1; cvt.u32.u64 %0, t; }" : "=r"(a) : "l"(p));
    return a;
}
#define CPA16(d, s) asm volatile("cp.async.cg.shared.global [%0], [%1], 16;" :: "r"(d), "l"(s))
#define CP_COMMIT() asm volatile("cp.async.commit_group;" ::: "memory")
#define CP_WAIT1()  asm volatile("cp.async.wait_group 1;" ::: "memory")
#define CP_WAIT0()  asm volatile("cp.async.wait_group 0;" ::: "memory")

__device__ __forceinline__ void ldm4(uint32_t addr, uint32_t* r){
    asm volatile("ldmatrix.sync.aligned.m8n8.x4.shared.b16 {%0,%1,%2,%3}, [%4];"
        : "=r"(r[0]), "=r"(r[1]), "=r"(r[2]), "=r"(r[3]) : "r"(addr));
}
__device__ __forceinline__ void mma16816(float* c, const uint32_t* a, const uint32_t* b){
    asm volatile("mma.sync.aligned.m16n8k16.row.col.f32.f16.f16.f32 "
        "{%0,%1,%2,%3}, {%4,%5,%6,%7}, {%8,%9}, {%0,%1,%2,%3};"
        : "+f"(c[0]), "+f"(c[1]), "+f"(c[2]), "+f"(c[3])
        : "r"(a[0]), "r"(a[1]), "r"(a[2]), "r"(a[3]), "r"(b[0]), "r"(b[1]));
}

// ---------------- scratch ----------------
__device__ __align__(256) __half g_pat[MALL*PATCHES];
__device__ __align__(256) __half g_cw[NDIM*PATCHES];
__device__ __align__(256) __half g_wqkvT[NDEPTH*QKVW*NDIM];
__device__ __align__(256) __half g_woT[NDEPTH*NDIM*NDIM];
__device__ __align__(256) __half g_w1T[NDEPTH*DMLP*NDIM];
__device__ __align__(256) __half g_w2T[NDEPTH*NDIM*DMLP];
__device__ __align__(256) float  g_x[MALL*NDIM];
__device__ __align__(256) __half g_h[MALL*NDIM];
__device__ __align__(256) __half g_qkv[MALL*QKVW];
__device__ __align__(256) float  g_scores[NBH*NTOK*NTOK];
__device__ __align__(256) __half g_p[NBH*NTOK*NTOK];
__device__ __align__(256) __half g_vt[NBH*DHEAD*NTOK];
__device__ __align__(256) __half g_o[MALL*NDIM];
__device__ __align__(256) __half g_m[MALL*DMLP];

// ---------------- prep kernels ----------------
__global__ void im2col_half(const float* __restrict__ vol, __half* __restrict__ o){
    int idx = blockIdx.x * 256 + threadIdx.x;
    int m = idx & 511, tkn = idx >> 9, n = tkn & 511, b = tkn >> 9;
    int k = m & 7, j = (m >> 3) & 7, i = m >> 6;
    int pw = n & 7, ph = (n >> 3) & 7, pd = n >> 6;
    o[idx] = __float2half_rn(vol[((long)b << 18) + (pd*8+i)*4096 + (ph*8+j)*64 + (pw*8+k)]);
}
__global__ void conv_half(const float* __restrict__ in, __half* __restrict__ o, int n){
    int idx = blockIdx.x * 256 + threadIdx.x;
    if (idx >= n) return;
    o[idx] = __float2half_rn(in[idx]);
}
// transpose+convert: fp32 [L][R][C] -> fp16 [L][C][R], 64R x 32C tiles
__global__ void wt_half(const float* __restrict__ in, __half* __restrict__ o, int R, int C){
    __shared__ float tf[64][33];
    int z = blockIdx.z;
    const float* ip = in + (long)z * R * C;
    int r0 = blockIdx.y * 64, c0 = blockIdx.x * 32;
    int tx = threadIdx.x, ty = threadIdx.y;   // 32 x 8
#pragma unroll
    for (int i = 0; i < 8; i++)
        tf[ty + 8*i][tx] = ip[(long)(r0 + ty + 8*i) * C + c0 + tx];
    __syncthreads();
    long ob = (long)z * R * C;
#pragma unroll
    for (int i = 0; i < 4; i++) {
        int c = ty + 8*i;
        int r = tx * 2;
        __half2 v = __halves2half2(__float2half_rn(tf[r][c]),
                                   __float2half_rn(tf[r+1][c]));
        *reinterpret_cast<__half2*>(&o[ob + (long)(c0 + c) * R + r0 + r]) = v;
    }
}

// ---------------- LN: single-pass, fp16 or fp32 out ----------------
template <int HALF>
__global__ void ln_kernel(const float* __restrict__ x, const float* __restrict__ w,
                          const float* __restrict__ bb, float* __restrict__ of,
                          __half* __restrict__ oh){
    __shared__ float red1[8], red2[8];
    const int row = blockIdx.x, t = threadIdx.x;
    const float* xp = x + (long)row * NDIM;
    float v0 = xp[t], v1 = xp[t+256], v2 = xp[t+512];
    float s1 = v0 + v1 + v2;
    float s2 = v0*v0 + v1*v1 + v2*v2;
#pragma unroll
    for (int o = 16; o; o >>= 1) {
        s1 += __shfl_xor_sync(~0u, s1, o);
        s2 += __shfl_xor_sync(~0u, s2, o);
    }
    if ((t & 31) == 0) { red1[t >> 5] = s1; red2[t >> 5] = s2; }
    __syncthreads();
    if (t < 32) {
        float r1 = (t < 8) ? red1[t] : 0.0f;
        float r2 = (t < 8) ? red2[t] : 0.0f;
#pragma unroll
        for (int o = 4; o; o >>= 1) {
            r1 += __shfl_xor_sync(~0u, r1, o);
            r2 += __shfl_xor_sync(~0u, r2, o);
        }
        if (t == 0) { red1[0] = r1; red2[0] = r2; }
    }
    __syncthreads();
    float mean = red1[0] * (1.0f / NDIM);
    float var  = red2[0] * (1.0f / NDIM) - mean * mean;
    float rs = rsqrtf(var + 1e-5f);
    float y0 = (v0-mean)*rs*w[t]     + bb[t];
    float y1 = (v1-mean)*rs*w[t+256] + bb[t+256];
    float y2 = (v2-mean)*rs*w[t+512] + bb[t+512];
    long o0 = (long)row * NDIM;
    if (HALF) {
        oh[o0+t]     = __float2half_rn(y0);
        oh[o0+t+256] = __float2half_rn(y1);
        oh[o0+t+512] = __float2half_rn(y2);
    } else {
        of[o0+t]=y0; of[o0+t+256]=y1; of[o0+t+512]=y2;
    }
}

// ---------------- softmax (fp32 scores -> fp16 P) ----------------
__global__ void softmax_half(const float* __restrict__ sc, __half* __restrict__ ph){
    __shared__ float redm[4], reds[4];
    long rb = (long)blockIdx.x * NTOK;
    const int t = threadIdx.x;
    float4 v = *reinterpret_cast<const float4*>(&sc[rb + t*4]);
    float m = fmaxf(fmaxf(v.x, v.y), fmaxf(v.z, v.w));
#pragma unroll
    for (int o = 16; o; o >>= 1) m = fmaxf(m, __shfl_xor_sync(~0u, m, o));
    if ((t & 31) == 0) redm[t >> 5] = m;
    __syncthreads();
    m = fmaxf(fmaxf(redm[0], redm[1]), fmaxf(redm[2], redm[3]));
    v.x = __expf(v.x-m); v.y = __expf(v.y-m); v.z = __expf(v.z-m); v.w = __expf(v.w-m);
    float s = v.x + v.y + v.z + v.w;
#pragma unroll
    for (int o = 16; o; o >>= 1) s += __shfl_xor_sync(~0u, s, o);
    if ((t & 31) == 0) reds[t >> 5] = s;
    __syncthreads();
    s = reds[0] + reds[1] + reds[2] + reds[3];
    float inv = 1.0f / s;
    long off = rb + t*4;
    reinterpret_cast<__half2*>(ph+off)[0] =
        __halves2half2(__float2half_rn(v.x*inv), __float2half_rn(v.y*inv));
    reinterpret_cast<__half2*>(ph+off)[1] =
        __halves2half2(__float2half_rn(v.z*inv), __float2half_rn(v.w*inv));
}

// ---------------- pure-fp16 GEMM via mma.sync ----------------
// C[M,N] = A[M,K] @ B[N,K]^T. 3-stage cp.async ring.
// EPI: 0 fp32*scale | 1 fp32 residual+=acc+bias | 2 tanh(acc+bias)->fp16
//      3 acc+bias+pos->fp32 | 4 acc->fp16 | 5 qkv fused (Q,K rows; V->vt transposed)
template <int BM, int BN>
__device__ __forceinline__ void ld_stage(uint32_t sb, int tid,
    const __half* pA, const __half* pB,
    long long lda, long long ldb, int row0, int col0, int k0){
    constexpr int ASZ = BM*80;
#pragma unroll
    for (int i = 0; i < BM/64; i++) {
        int ch = tid + i*256;
        int r = ch >> 2, c = ch & 3;
        uint32_t so = r*80 + c*16;
        CPA16(sb + so, pA + (long long)(row0 + r) * lda + k0 + c*8);
    }
#pragma unroll
    for (int i = 0; i < BN/64; i++) {
        int ch = tid + i*256;
        int r = ch >> 2, c = ch & 3;
        uint32_t so = r*80 + c*16;
        CPA16(sb + ASZ + so, pB + (long long)(col0 + r) * ldb + k0 + c*8);
    }
}

template <int BM, int BN, int EPI, int OCC>
__global__ void __launch_bounds__(256, OCC) mma_gemm(
    const __half* __restrict__ A, long long lda, long long aSB, long long aSH,
    const __half* __restrict__ B, long long ldb, long long bSB, long long bSH,
    float* __restrict__ Cf, __half* __restrict__ Oh, __half* __restrict__ Vt,
    long long ldc, long long cSB, long long cSH,
    const float* __restrict__ bias, const float* __restrict__ pos,
    float scale, int K, int heads)
{
    extern __shared__ __align__(128) char smem_raw[];
    uint32_t sb = smem_u32(smem_raw);
    constexpr int ASZ = BM*80;
    constexpr int BUF = (BM+BN)*80;
    constexpr int MW = BM/32;
    constexpr int NW = 8/MW;
    constexpr int WN = BN/NW;
    constexpr int NP = WN/16;
    constexpr int NT = WN/8;

    const int tid = threadIdx.x, lane = tid & 31, warp = tid >> 5;
    const int warpM = warp % MW, warpN = warp / MW;
    const int z = blockIdx.z, zb = z / heads, zh = z % heads;
    const __half* pA = A + zb*aSB + zh*aSH;
    const __half* pB = B + zb*bSB + zh*bSH;
    const long long cOff = zb*cSB + zh*cSH;
    const int row0 = blockIdx.y * BM, col0 = blockIdx.x * BN;

    float acc[2][NT][4];
#pragma unroll
    for (int a = 0; a < 2; a++)
#pragma unroll
        for (int b = 0; b < NT; b++)
#pragma unroll
            for (int c = 0; c < 4; c++) acc[a][b][c] = 0.0f;

    const int nst = K >> 5;
    ld_stage<BM,BN>(sb, tid, pA, pB, lda, ldb, row0, col0, 0);
    CP_COMMIT();
    if (nst > 1) {
        ld_stage<BM,BN>(sb + BUF, tid, pA, pB, lda, ldb, row0, col0, 32);
        CP_COMMIT();
    }

    const int L = lane & 7, jj = lane >> 3;
    for (int st = 0; st < nst; st++) {
        if (st < nst - 1) CP_WAIT1(); else CP_WAIT0();
        __syncthreads();
        if (st + 2 < nst) {
            ld_stage<BM,BN>(sb + ((st+2)%3)*BUF, tid, pA, pB,
                            lda, ldb, row0, col0, (st+2)*32);
            CP_COMMIT();
        }
        uint32_t base = sb + (st % 3) * BUF;
#pragma unroll
        for (int ks = 0; ks < 2; ks++) {
            uint32_t a_[2][4];
#pragma unroll
            for (int mi = 0; mi < 2; mi++) {
                int mrow = warpM*32 + mi*16 + (jj & 1)*8 + L;
                int kcol = ks*16 + (jj >> 1)*8;
                ldm4(base + mrow*80 + kcol*2, a_[mi]);
            }
            uint32_t b_[NP][4];
#pragma unroll
            for (int np = 0; np < NP; np++) {
                int nrow = warpN*WN + np*16 + (jj >> 1)*8 + L;
                int kcol = ks*16 + (jj & 1)*8;
                ldm4(base + ASZ + nrow*80 + kcol*2, b_[np]);
            }
#pragma unroll
            for (int mi = 0; mi < 2; mi++)
#pragma unroll
                for (int np = 0; np < NP; np++)
#pragma unroll
                    for (int si = 0; si < 2; si++) {
                        uint32_t f[2] = { b_[np][si*2], b_[np][si*2+1] };
                        mma16816(acc[mi][np*2 + si], a_[mi], f);
                    }
        }
    }

#pragma unroll
    for (int mi = 0; mi < 2; mi++)
#pragma unroll
        for (int nt = 0; nt < NT; nt++) {
            float* c = acc[mi][nt];
            int col = col0 + warpN*WN + nt*8 + (lane & 3)*2;
#pragma unroll
            for (int hf = 0; hf < 2; hf++) {
                int row = row0 + warpM*32 + mi*16 + (lane >> 2) + hf*8;
                float v0 = c[hf*2 + 0], v1 = c[hf*2 + 1];
                if (EPI == 0) {
                    float2* cp = reinterpret_cast<float2*>(Cf + cOff + (long long)row*ldc + col);
                    *cp = make_float2(v0*scale, v1*scale);
                } else if (EPI == 1) {
                    float2* cp = reinterpret_cast<float2*>(Cf + cOff + (long long)row*ldc + col);
                    float2 old = *cp;
                    *cp = make_float2(old.x + v0 + bias[col], old.y + v1 + bias[col+1]);
                } else if (EPI == 3) {
                    const float2* pp = reinterpret_cast<const float2*>(
                        pos + (long long)(row & (NTOK-1))*ldc + col);
                    float2 pv = *pp;
                    float2* cp = reinterpret_cast<float2*>(Cf + (long long)row*ldc + col);
                    *cp = make_float2(v0 + bias[col] + pv.x, v1 + bias[col+1] + pv.y);
                } else if (EPI == 5) {
                    if (col0 < 2*NDIM) {
                        long long off = (long long)row*ldc + col;
                        *reinterpret_cast<__half2*>(Oh + off) =
                            __halves2half2(__float2half_rn(v0), __float2half_rn(v1));
                    } else {
                        int bb2 = row >> 9, t2 = row & (NTOK-1);
                        int hd = col - 2*NDIM, hh2 = hd >> 6, d = hd & (DHEAD-1);
                        long vtb = ((long)(bb2*NHEADS + hh2)*DHEAD + d)*NTOK + t2;
                        Vt[vtb] = __float2half_rn(v0);
                        Vt[vtb + NTOK] = __float2half_rn(v1);
                    }
                } else {
                    if (EPI == 2) {
                        v0 = tanhf(v0 + bias[col]);
                        v1 = tanhf(v1 + bias[col+1]);
                    }
                    long long off = cOff + (long long)row*ldc + col;
                    *reinterpret_cast<__half2*>(Oh + off) =
                        __halves2half2(__float2half_rn(v0), __float2half_rn(v1));
                }
            }
        }
}

// ---------------- host ----------------
extern "C" void kernel_launch(void* const* d_in, const int* in_sizes, int n_in,
                              void* d_out, int out_size)
{
    const float* volume    = (const float*)d_in[0];
    const float* conv_w    = (const float*)d_in[1];
    const float* conv_b    = (const float*)d_in[2];
    const float* pos_embed = (const float*)d_in[3];
    const float* ln1_w     = (const float*)d_in[4];
    const float* ln1_b     = (const float*)d_in[5];
    const float* w_qkv     = (const float*)d_in[6];
    const float* w_o       = (const float*)d_in[7];
    const float* b_o       = (const float*)d_in[8];
    const float* ln2_w     = (const float*)d_in[9];
    const float* ln2_b     = (const float*)d_in[10];
    const float* w1        = (const float*)d_in[11];
    const float* b1        = (const float*)d_in[12];
    const float* w2        = (const float*)d_in[13];
    const float* b2        = (const float*)d_in[14];
    const float* lnf_w     = (const float*)d_in[15];
    const float* lnf_b     = (const float*)d_in[16];
    float* out = (float*)d_out;

    __half *pat,*cw,*wqT,*woT,*w1T,*w2T,*h,*qkv,*p,*vt,*o,*m;
    float *x, *scores;
    cudaGetSymbolAddress((void**)&pat, g_pat);
    cudaGetSymbolAddress((void**)&cw, g_cw);
    cudaGetSymbolAddress((void**)&wqT, g_wqkvT);
    cudaGetSymbolAddress((void**)&woT, g_woT);
    cudaGetSymbolAddress((void**)&w1T, g_w1T);
    cudaGetSymbolAddress((void**)&w2T, g_w2T);
    cudaGetSymbolAddress((void**)&x, g_x);
    cudaGetSymbolAddress((void**)&h, g_h);
    cudaGetSymbolAddress((void**)&qkv, g_qkv);
    cudaGetSymbolAddress((void**)&scores, g_scores);
    cudaGetSymbolAddress((void**)&p, g_p);
    cudaGetSymbolAddress((void**)&vt, g_vt);
    cudaGetSymbolAddress((void**)&o, g_o);
    cudaGetSymbolAddress((void**)&m, g_m);

    const int S_128_128 = 3*(128+128)*80;   // 61440
    const int S_64_64   = 3*(64+64)*80;     // 30720
    cudaFuncSetAttribute((const void*)mma_gemm<128,128,5,2>, cudaFuncAttributeMaxDynamicSharedMemorySize, S_128_128);
    cudaFuncSetAttribute((const void*)mma_gemm<128,128,0,2>, cudaFuncAttributeMaxDynamicSharedMemorySize, S_128_128);
    cudaFuncSetAttribute((const void*)mma_gemm<128,128,2,2>, cudaFuncAttributeMaxDynamicSharedMemorySize, S_128_128);
    cudaFuncSetAttribute((const void*)mma_gemm<64,64,4,2>,   cudaFuncAttributeMaxDynamicSharedMemorySize, S_64_64);
    cudaFuncSetAttribute((const void*)mma_gemm<64,64,1,2>,   cudaFuncAttributeMaxDynamicSharedMemorySize, S_64_64);
    cudaFuncSetAttribute((const void*)mma_gemm<64,64,3,2>,   cudaFuncAttributeMaxDynamicSharedMemorySize, S_64_64);

    dim3 tb(32, 8);

    im2col_half<<<(MALL*PATCHES)/256, 256>>>(volume, pat);
    conv_half<<<(NDIM*PATCHES)/256, 256>>>(conv_w, cw, NDIM*PATCHES);
    wt_half<<<dim3(QKVW/32, NDIM/64, NDEPTH), tb>>>(w_qkv, wqT, NDIM, QKVW);
    wt_half<<<dim3(NDIM/32, NDIM/64, NDEPTH), tb>>>(w_o, woT, NDIM, NDIM);
    wt_half<<<dim3(DMLP/32, NDIM/64, NDEPTH), tb>>>(w1, w1T, NDIM, DMLP);
    wt_half<<<dim3(NDIM/32, DMLP/64, NDEPTH), tb>>>(w2, w2T, DMLP, NDIM);

    // patch embed: x = patches @ conv_w^T + conv_b + pos  (192 CTAs)
    mma_gemm<64,64,3,2><<<dim3(NDIM/64, MALL/64, 1), 256, S_64_64>>>(
        pat, PATCHES, 0, 0, cw, PATCHES, 0, 0,
        x, nullptr, nullptr, NDIM, 0, 0, conv_b, pos_embed, 1.f, PATCHES, 1);

    for (int l = 0; l < NDEPTH; ++l) {
        ln_kernel<1><<<MALL, 256>>>(x, ln1_w + l*NDIM, ln1_b + l*NDIM, nullptr, h);
        // QKV fused: Q,K rows stored; V transposed into vt (144 CTAs)
        mma_gemm<128,128,5,2><<<dim3(QKVW/128, MALL/128, 1), 256, S_128_128>>>(
            h, NDIM, 0, 0, wqT + (long)l*QKVW*NDIM, NDIM, 0, 0,
            nullptr, qkv, vt, QKVW, 0, 0, nullptr, nullptr, 1.f, NDIM, 1);
        // QK (384 CTAs)
        mma_gemm<128,128,0,2><<<dim3(NTOK/128, NTOK/128, NBH), 256, S_128_128>>>(
            qkv, QKVW, (long long)NTOK*QKVW, DHEAD,
            qkv + NDIM, QKVW, (long long)NTOK*QKVW, DHEAD,
            scores, nullptr, nullptr, NTOK, (long long)NHEADS*NTOK*NTOK, (long long)NTOK*NTOK,
            nullptr, nullptr, 0.125f, DHEAD, NHEADS);
        softmax_half<<<NBH*NTOK, 128>>>(scores, p);
        // PV (192 CTAs)
        mma_gemm<64,64,4,2><<<dim3(1, NTOK/64, NBH), 256, S_64_64>>>(
            p, NTOK, (long long)NHEADS*NTOK*NTOK, (long long)NTOK*NTOK,
            vt, NTOK, (long long)NHEADS*DHEAD*NTOK, (long long)DHEAD*NTOK,
            nullptr, o, nullptr, NDIM, (long long)NTOK*NDIM, DHEAD,
            nullptr, nullptr, 1.f, NTOK, NHEADS);
        // O-proj (192 CTAs)
        mma_gemm<64,64,1,2><<<dim3(NDIM/64, MALL/64, 1), 256, S_64_64>>>(
            o, NDIM, 0, 0, woT + (long)l*NDIM*NDIM, NDIM, 0, 0,
            x, nullptr, nullptr, NDIM, 0, 0, b_o + l*NDIM, nullptr, 1.f, NDIM, 1);
        ln_kernel<1><<<MALL, 256>>>(x, ln2_w + l*NDIM, ln2_b + l*NDIM, nullptr, h);
        // MLP1 retiled to 128x128 (192 CTAs, was 128x192 / 128 CTAs)
        mma_gemm<128,128,2,2><<<dim3(DMLP/128, MALL/128, 1), 256, S_128_128>>>(
            h, NDIM, 0, 0, w1T + (long)l*DMLP*NDIM, NDIM, 0, 0,
            nullptr, m, nullptr, DMLP, 0, 0, b1 + l*DMLP, nullptr, 1.f, NDIM, 1);
        // MLP2 (192 CTAs)
        mma_gemm<64,64,1,2><<<dim3(NDIM/64, MALL/64, 1), 256, S_64_64>>>(
            m, DMLP, 0, 0, w2T + (long)l*NDIM*DMLP, DMLP, 0, 0,
            x, nullptr, nullptr, NDIM, 0, 0, b2 + l*NDIM, nullptr, 1.f, DMLP, 1);
    }

    ln_kernel<0><<<MALL, 256>>>(x, lnf_w, lnf_b, out, nullptr);
}

// round 15
// speedup vs baseline: 1.0657x; 1.0257x over previous
#include <cuda_runtime.h>
#include <cuda_fp16.h>
#include <cstdint>
#include <math.h>

#define NDIM 768
#define NTOK 512
#define BSZ 2
#define MALL 1024
#define NHEADS 12
#define DHEAD 64
#define DMLP 3072
#define NDEPTH 4
#define QKVW 2304
#define PATCHES 512
#define NBH (BSZ*NHEADS)

__device__ __forceinline__ uint32_t smem_u32(const void* p){
    uint32_t a;
    asm("{ .reg .u64 t; cvta.to.shared.u64 t, %1; cvt.u32.u64 %0, t; }" : "=r"(a) : "l"(p));
    return a;
}
#define CPA16(d, s) asm volatile("cp.async.cg.shared.global [%0], [%1], 16;" :: "r"(d), "l"(s))
#define CP_COMMIT() asm volatile("cp.async.commit_group;" ::: "memory")
#define CP_WAIT1()  asm volatile("cp.async.wait_group 1;" ::: "memory")
#define CP_WAIT0()  asm volatile("cp.async.wait_group 0;" ::: "memory")

__device__ __forceinline__ void ldm4(uint32_t addr, uint32_t* r){
    asm volatile("ldmatrix.sync.aligned.m8n8.x4.shared.b16 {%0,%1,%2,%3}, [%4];"
        : "=r"(r[0]), "=r"(r[1]), "=r"(r[2]), "=r"(r[3]) : "r"(addr));
}
__device__ __forceinline__ void mma16816(float* c, const uint32_t* a, const uint32_t* b){
    asm volatile("mma.sync.aligned.m16n8k16.row.col.f32.f16.f16.f32 "
        "{%0,%1,%2,%3}, {%4,%5,%6,%7}, {%8,%9}, {%0,%1,%2,%3};"
        : "+f"(c[0]), "+f"(c[1]), "+f"(c[2]), "+f"(c[3])
        : "r"(a[0]), "r"(a[1]), "r"(a[2]), "r"(a[3]), "r"(b[0]), "r"(b[1]));
}

// ---------------- scratch ----------------
__device__ __align__(256) __half g_pat[MALL*PATCHES];
__device__ __align__(256) __half g_cw[NDIM*PATCHES];
__device__ __align__(256) __half g_wqkvT[NDEPTH*QKVW*NDIM];
__device__ __align__(256) __half g_woT[NDEPTH*NDIM*NDIM];
__device__ __align__(256) __half g_w1T[NDEPTH*DMLP*NDIM];
__device__ __align__(256) __half g_w2T[NDEPTH*NDIM*DMLP];
__device__ __align__(256) float  g_x[MALL*NDIM];
__device__ __align__(256) __half g_h[MALL*NDIM];
__device__ __align__(256) __half g_qkv[MALL*QKVW];
__device__ __align__(256) __half g_p[NBH*NTOK*NTOK];
__device__ __align__(256) __half g_vt[NBH*DHEAD*NTOK];
__device__ __align__(256) __half g_o[MALL*NDIM];
__device__ __align__(256) __half g_m[MALL*DMLP];

// ---------------- prep kernels ----------------
__global__ void im2col_half(const float* __restrict__ vol, __half* __restrict__ o){
    int idx = blockIdx.x * 256 + threadIdx.x;
    int m = idx & 511, tkn = idx >> 9, n = tkn & 511, b = tkn >> 9;
    int k = m & 7, j = (m >> 3) & 7, i = m >> 6;
    int pw = n & 7, ph = (n >> 3) & 7, pd = n >> 6;
    o[idx] = __float2half_rn(vol[((long)b << 18) + (pd*8+i)*4096 + (ph*8+j)*64 + (pw*8+k)]);
}
__global__ void conv_half(const float* __restrict__ in, __half* __restrict__ o, int n){
    int idx = blockIdx.x * 256 + threadIdx.x;
    if (idx >= n) return;
    o[idx] = __float2half_rn(in[idx]);
}
// transpose+convert: fp32 [L][R][C] -> fp16 [L][C][R], 64R x 32C tiles
__global__ void wt_half(const float* __restrict__ in, __half* __restrict__ o, int R, int C){
    __shared__ float tf[64][33];
    int z = blockIdx.z;
    const float* ip = in + (long)z * R * C;
    int r0 = blockIdx.y * 64, c0 = blockIdx.x * 32;
    int tx = threadIdx.x, ty = threadIdx.y;   // 32 x 8
#pragma unroll
    for (int i = 0; i < 8; i++)
        tf[ty + 8*i][tx] = ip[(long)(r0 + ty + 8*i) * C + c0 + tx];
    __syncthreads();
    long ob = (long)z * R * C;
#pragma unroll
    for (int i = 0; i < 4; i++) {
        int c = ty + 8*i;
        int r = tx * 2;
        __half2 v = __halves2half2(__float2half_rn(tf[r][c]),
                                   __float2half_rn(tf[r+1][c]));
        *reinterpret_cast<__half2*>(&o[ob + (long)(c0 + c) * R + r0 + r]) = v;
    }
}

// ---------------- LN: single-pass, fp16 or fp32 out ----------------
template <int HALF>
__global__ void ln_kernel(const float* __restrict__ x, const float* __restrict__ w,
                          const float* __restrict__ bb, float* __restrict__ of,
                          __half* __restrict__ oh){
    __shared__ float red1[8], red2[8];
    const int row = blockIdx.x, t = threadIdx.x;
    const float* xp = x + (long)row * NDIM;
    float v0 = xp[t], v1 = xp[t+256], v2 = xp[t+512];
    float s1 = v0 + v1 + v2;
    float s2 = v0*v0 + v1*v1 + v2*v2;
#pragma unroll
    for (int o = 16; o; o >>= 1) {
        s1 += __shfl_xor_sync(~0u, s1, o);
        s2 += __shfl_xor_sync(~0u, s2, o);
    }
    if ((t & 31) == 0) { red1[t >> 5] = s1; red2[t >> 5] = s2; }
    __syncthreads();
    if (t < 32) {
        float r1 = (t < 8) ? red1[t] : 0.0f;
        float r2 = (t < 8) ? red2[t] : 0.0f;
#pragma unroll
        for (int o = 4; o; o >>= 1) {
            r1 += __shfl_xor_sync(~0u, r1, o);
            r2 += __shfl_xor_sync(~0u, r2, o);
        }
        if (t == 0) { red1[0] = r1; red2[0] = r2; }
    }
    __syncthreads();
    float mean = red1[0] * (1.0f / NDIM);
    float var  = red2[0] * (1.0f / NDIM) - mean * mean;
    float rs = rsqrtf(var + 1e-5f);
    float y0 = (v0-mean)*rs*w[t]     + bb[t];
    float y1 = (v1-mean)*rs*w[t+256] + bb[t+256];
    float y2 = (v2-mean)*rs*w[t+512] + bb[t+512];
    long o0 = (long)row * NDIM;
    if (HALF) {
        oh[o0+t]     = __float2half_rn(y0);
        oh[o0+t+256] = __float2half_rn(y1);
        oh[o0+t+512] = __float2half_rn(y2);
    } else {
        of[o0+t]=y0; of[o0+t+256]=y1; of[o0+t+512]=y2;
    }
}

// ---------------- softmax, in-place on fp16 scores/P ----------------
__global__ void softmax_half(__half* __restrict__ ph){
    __shared__ float redm[4], reds[4];
    long rb = (long)blockIdx.x * NTOK;
    const int t = threadIdx.x;
    __half2 h0 = reinterpret_cast<const __half2*>(ph + rb + t*4)[0];
    __half2 h1 = reinterpret_cast<const __half2*>(ph + rb + t*4)[1];
    float v0 = __half2float(h0.x), v1 = __half2float(h0.y);
    float v2 = __half2float(h1.x), v3 = __half2float(h1.y);
    float m = fmaxf(fmaxf(v0, v1), fmaxf(v2, v3));
#pragma unroll
    for (int o = 16; o; o >>= 1) m = fmaxf(m, __shfl_xor_sync(~0u, m, o));
    if ((t & 31) == 0) redm[t >> 5] = m;
    __syncthreads();
    m = fmaxf(fmaxf(redm[0], redm[1]), fmaxf(redm[2], redm[3]));
    v0 = __expf(v0-m); v1 = __expf(v1-m); v2 = __expf(v2-m); v3 = __expf(v3-m);
    float s = v0 + v1 + v2 + v3;
#pragma unroll
    for (int o = 16; o; o >>= 1) s += __shfl_xor_sync(~0u, s, o);
    if ((t & 31) == 0) reds[t >> 5] = s;
    __syncthreads();
    s = reds[0] + reds[1] + reds[2] + reds[3];
    float inv = 1.0f / s;
    reinterpret_cast<__half2*>(ph + rb + t*4)[0] =
        __halves2half2(__float2half_rn(v0*inv), __float2half_rn(v1*inv));
    reinterpret_cast<__half2*>(ph + rb + t*4)[1] =
        __halves2half2(__float2half_rn(v2*inv), __float2half_rn(v3*inv));
}

// ---------------- pure-fp16 GEMM via mma.sync ----------------
// C[M,N] = A[M,K] @ B[N,K]^T. 3-stage cp.async ring.
// EPI: 0 fp16 acc*scale | 1 fp32 residual+=acc+bias | 2 tanh(acc+bias)->fp16
//      3 acc+bias+pos->fp32 | 4 acc->fp16 | 5 qkv fused (Q,K rows; V->vt transposed)
template <int BM, int BN>
__device__ __forceinline__ void ld_stage(uint32_t sb, int tid,
    const __half* pA, const __half* pB,
    long long lda, long long ldb, int row0, int col0, int k0){
    constexpr int ASZ = BM*80;
#pragma unroll
    for (int i = 0; i < BM/64; i++) {
        int ch = tid + i*256;
        int r = ch >> 2, c = ch & 3;
        uint32_t so = r*80 + c*16;
        CPA16(sb + so, pA + (long long)(row0 + r) * lda + k0 + c*8);
    }
#pragma unroll
    for (int i = 0; i < BN/64; i++) {
        int ch = tid + i*256;
        int r = ch >> 2, c = ch & 3;
        uint32_t so = r*80 + c*16;
        CPA16(sb + ASZ + so, pB + (long long)(col0 + r) * ldb + k0 + c*8);
    }
}

template <int BM, int BN, int EPI, int OCC>
__global__ void __launch_bounds__(256, OCC) mma_gemm(
    const __half* __restrict__ A, long long lda, long long aSB, long long aSH,
    const __half* __restrict__ B, long long ldb, long long bSB, long long bSH,
    float* __restrict__ Cf, __half* __restrict__ Oh, __half* __restrict__ Vt,
    long long ldc, long long cSB, long long cSH,
    const float* __restrict__ bias, const float* __restrict__ pos,
    float scale, int K, int heads)
{
    extern __shared__ __align__(128) char smem_raw[];
    uint32_t sb = smem_u32(smem_raw);
    constexpr int ASZ = BM*80;
    constexpr int BUF = (BM+BN)*80;
    constexpr int MW = BM/32;
    constexpr int NW = 8/MW;
    constexpr int WN = BN/NW;
    constexpr int NP = WN/16;
    constexpr int NT = WN/8;

    const int tid = threadIdx.x, lane = tid & 31, warp = tid >> 5;
    const int warpM = warp % MW, warpN = warp / MW;
    const int z = blockIdx.z, zb = z / heads, zh = z % heads;
    const __half* pA = A + zb*aSB + zh*aSH;
    const __half* pB = B + zb*bSB + zh*bSH;
    const long long cOff = zb*cSB + zh*cSH;
    const int row0 = blockIdx.y * BM, col0 = blockIdx.x * BN;

    float acc[2][NT][4];
#pragma unroll
    for (int a = 0; a < 2; a++)
#pragma unroll
        for (int b = 0; b < NT; b++)
#pragma unroll
            for (int c = 0; c < 4; c++) acc[a][b][c] = 0.0f;

    const int nst = K >> 5;
    ld_stage<BM,BN>(sb, tid, pA, pB, lda, ldb, row0, col0, 0);
    CP_COMMIT();
    if (nst > 1) {
        ld_stage<BM,BN>(sb + BUF, tid, pA, pB, lda, ldb, row0, col0, 32);
        CP_COMMIT();
    }

    const int L = lane & 7, jj = lane >> 3;
    for (int st = 0; st < nst; st++) {
        if (st < nst - 1) CP_WAIT1(); else CP_WAIT0();
        __syncthreads();
        if (st + 2 < nst) {
            ld_stage<BM,BN>(sb + ((st+2)%3)*BUF, tid, pA, pB,
                            lda, ldb, row0, col0, (st+2)*32);
            CP_COMMIT();
        }
        uint32_t base = sb + (st % 3) * BUF;
#pragma unroll
        for (int ks = 0; ks < 2; ks++) {
            uint32_t a_[2][4];
#pragma unroll
            for (int mi = 0; mi < 2; mi++) {
                int mrow = warpM*32 + mi*16 + (jj & 1)*8 + L;
                int kcol = ks*16 + (jj >> 1)*8;
                ldm4(base + mrow*80 + kcol*2, a_[mi]);
            }
            uint32_t b_[NP][4];
#pragma unroll
            for (int np = 0; np < NP; np++) {
                int nrow = warpN*WN + np*16 + (jj >> 1)*8 + L;
                int kcol = ks*16 + (jj & 1)*8;
                ldm4(base + ASZ + nrow*80 + kcol*2, b_[np]);
            }
#pragma unroll
            for (int mi = 0; mi < 2; mi++)
#pragma unroll
                for (int np = 0; np < NP; np++)
#pragma unroll
                    for (int si = 0; si < 2; si++) {
                        uint32_t f[2] = { b_[np][si*2], b_[np][si*2+1] };
                        mma16816(acc[mi][np*2 + si], a_[mi], f);
                    }
        }
    }

#pragma unroll
    for (int mi = 0; mi < 2; mi++)
#pragma unroll
        for (int nt = 0; nt < NT; nt++) {
            float* c = acc[mi][nt];
            int col = col0 + warpN*WN + nt*8 + (lane & 3)*2;
#pragma unroll
            for (int hf = 0; hf < 2; hf++) {
                int row = row0 + warpM*32 + mi*16 + (lane >> 2) + hf*8;
                float v0 = c[hf*2 + 0], v1 = c[hf*2 + 1];
                if (EPI == 0) {
                    long long off = cOff + (long long)row*ldc + col;
                    *reinterpret_cast<__half2*>(Oh + off) =
                        __halves2half2(__float2half_rn(v0*scale), __float2half_rn(v1*scale));
                } else if (EPI == 1) {
                    float2* cp = reinterpret_cast<float2*>(Cf + cOff + (long long)row*ldc + col);
                    float2 old = *cp;
                    *cp = make_float2(old.x + v0 + bias[col], old.y + v1 + bias[col+1]);
                } else if (EPI == 3) {
                    const float2* pp = reinterpret_cast<const float2*>(
                        pos + (long long)(row & (NTOK-1))*ldc + col);
                    float2 pv = *pp;
                    float2* cp = reinterpret_cast<float2*>(Cf + (long long)row*ldc + col);
                    *cp = make_float2(v0 + bias[col] + pv.x, v1 + bias[col+1] + pv.y);
                } else if (EPI == 5) {
                    if (col0 < 2*NDIM) {
                        long long off = (long long)row*ldc + col;
                        *reinterpret_cast<__half2*>(Oh + off) =
                            __halves2half2(__float2half_rn(v0), __float2half_rn(v1));
                    } else {
                        int bb2 = row >> 9, t2 = row & (NTOK-1);
                        int hd = col - 2*NDIM, hh2 = hd >> 6, d = hd & (DHEAD-1);
                        long vtb = ((long)(bb2*NHEADS + hh2)*DHEAD + d)*NTOK + t2;
                        Vt[vtb] = __float2half_rn(v0);
                        Vt[vtb + NTOK] = __float2half_rn(v1);
                    }
                } else {
                    if (EPI == 2) {
                        v0 = tanhf(v0 + bias[col]);
                        v1 = tanhf(v1 + bias[col+1]);
                    }
                    long long off = cOff + (long long)row*ldc + col;
                    *reinterpret_cast<__half2*>(Oh + off) =
                        __halves2half2(__float2half_rn(v0), __float2half_rn(v1));
                }
            }
        }
}

// ---------------- host ----------------
extern "C" void kernel_launch(void* const* d_in, const int* in_sizes, int n_in,
                              void* d_out, int out_size)
{
    const float* volume    = (const float*)d_in[0];
    const float* conv_w    = (const float*)d_in[1];
    const float* conv_b    = (const float*)d_in[2];
    const float* pos_embed = (const float*)d_in[3];
    const float* ln1_w     = (const float*)d_in[4];
    const float* ln1_b     = (const float*)d_in[5];
    const float* w_qkv     = (const float*)d_in[6];
    const float* w_o       = (const float*)d_in[7];
    const float* b_o       = (const float*)d_in[8];
    const float* ln2_w     = (const float*)d_in[9];
    const float* ln2_b     = (const float*)d_in[10];
    const float* w1        = (const float*)d_in[11];
    const float* b1        = (const float*)d_in[12];
    const float* w2        = (const float*)d_in[13];
    const float* b2        = (const float*)d_in[14];
    const float* lnf_w     = (const float*)d_in[15];
    const float* lnf_b     = (const float*)d_in[16];
    float* out = (float*)d_out;

    __half *pat,*cw,*wqT,*woT,*w1T,*w2T,*h,*qkv,*p,*vt,*o,*m;
    float *x;
    cudaGetSymbolAddress((void**)&pat, g_pat);
    cudaGetSymbolAddress((void**)&cw, g_cw);
    cudaGetSymbolAddress((void**)&wqT, g_wqkvT);
    cudaGetSymbolAddress((void**)&woT, g_woT);
    cudaGetSymbolAddress((void**)&w1T, g_w1T);
    cudaGetSymbolAddress((void**)&w2T, g_w2T);
    cudaGetSymbolAddress((void**)&x, g_x);
    cudaGetSymbolAddress((void**)&h, g_h);
    cudaGetSymbolAddress((void**)&qkv, g_qkv);
    cudaGetSymbolAddress((void**)&p, g_p);
    cudaGetSymbolAddress((void**)&vt, g_vt);
    cudaGetSymbolAddress((void**)&o, g_o);
    cudaGetSymbolAddress((void**)&m, g_m);

    const int S_128_128 = 3*(128+128)*80;   // 61440
    const int S_128_192 = 3*(128+192)*80;   // 76800
    const int S_64_64   = 3*(64+64)*80;     // 30720
    cudaFuncSetAttribute((const void*)mma_gemm<128,128,5,2>, cudaFuncAttributeMaxDynamicSharedMemorySize, S_128_128);
    cudaFuncSetAttribute((const void*)mma_gemm<128,128,0,2>, cudaFuncAttributeMaxDynamicSharedMemorySize, S_128_128);
    cudaFuncSetAttribute((const void*)mma_gemm<64,64,4,2>,   cudaFuncAttributeMaxDynamicSharedMemorySize, S_64_64);
    cudaFuncSetAttribute((const void*)mma_gemm<64,64,1,2>,   cudaFuncAttributeMaxDynamicSharedMemorySize, S_64_64);
    cudaFuncSetAttribute((const void*)mma_gemm<64,64,3,2>,   cudaFuncAttributeMaxDynamicSharedMemorySize, S_64_64);
    cudaFuncSetAttribute((const void*)mma_gemm<128,192,2,2>, cudaFuncAttributeMaxDynamicSharedMemorySize, S_128_192);

    dim3 tb(32, 8);

    im2col_half<<<(MALL*PATCHES)/256, 256>>>(volume, pat);
    conv_half<<<(NDIM*PATCHES)/256, 256>>>(conv_w, cw, NDIM*PATCHES);
    wt_half<<<dim3(QKVW/32, NDIM/64, NDEPTH), tb>>>(w_qkv, wqT, NDIM, QKVW);
    wt_half<<<dim3(NDIM/32, NDIM/64, NDEPTH), tb>>>(w_o, woT, NDIM, NDIM);
    wt_half<<<dim3(DMLP/32, NDIM/64, NDEPTH), tb>>>(w1, w1T, NDIM, DMLP);
    wt_half<<<dim3(NDIM/32, DMLP/64, NDEPTH), tb>>>(w2, w2T, DMLP, NDIM);

    // patch embed: x = patches @ conv_w^T + conv_b + pos  (192 CTAs)
    mma_gemm<64,64,3,2><<<dim3(NDIM/64, MALL/64, 1), 256, S_64_64>>>(
        pat, PATCHES, 0, 0, cw, PATCHES, 0, 0,
        x, nullptr, nullptr, NDIM, 0, 0, conv_b, pos_embed, 1.f, PATCHES, 1);

    for (int l = 0; l < NDEPTH; ++l) {
        ln_kernel<1><<<MALL, 256>>>(x, ln1_w + l*NDIM, ln1_b + l*NDIM, nullptr, h);
        // QKV fused: Q,K rows stored; V transposed into vt
        mma_gemm<128,128,5,2><<<dim3(QKVW/128, MALL/128, 1), 256, S_128_128>>>(
            h, NDIM, 0, 0, wqT + (long)l*QKVW*NDIM, NDIM, 0, 0,
            nullptr, qkv, vt, QKVW, 0, 0, nullptr, nullptr, 1.f, NDIM, 1);
        // QK -> fp16 scores directly into p
        mma_gemm<128,128,0,2><<<dim3(NTOK/128, NTOK/128, NBH), 256, S_128_128>>>(
            qkv, QKVW, (long long)NTOK*QKVW, DHEAD,
            qkv + NDIM, QKVW, (long long)NTOK*QKVW, DHEAD,
            nullptr, p, nullptr, NTOK, (long long)NHEADS*NTOK*NTOK, (long long)NTOK*NTOK,
            nullptr, nullptr, 0.125f, DHEAD, NHEADS);
        // softmax in-place on p
        softmax_half<<<NBH*NTOK, 128>>>(p);
        // PV (192 CTAs)
        mma_gemm<64,64,4,2><<<dim3(1, NTOK/64, NBH), 256, S_64_64>>>(
            p, NTOK, (long long)NHEADS*NTOK*NTOK, (long long)NTOK*NTOK,
            vt, NTOK, (long long)NHEADS*DHEAD*NTOK, (long long)DHEAD*NTOK,
            nullptr, o, nullptr, NDIM, (long long)NTOK*NDIM, DHEAD,
            nullptr, nullptr, 1.f, NTOK, NHEADS);
        // O-proj (192 CTAs)
        mma_gemm<64,64,1,2><<<dim3(NDIM/64, MALL/64, 1), 256, S_64_64>>>(
            o, NDIM, 0, 0, woT + (long)l*NDIM*NDIM, NDIM, 0, 0,
            x, nullptr, nullptr, NDIM, 0, 0, b_o + l*NDIM, nullptr, 1.f, NDIM, 1);
        ln_kernel<1><<<MALL, 256>>>(x, ln2_w + l*NDIM, ln2_b + l*NDIM, nullptr, h);
        // MLP1 (128x192, R12 config)
        mma_gemm<128,192,2,2><<<dim3(DMLP/192, MALL/128, 1), 256, S_128_192>>>(
            h, NDIM, 0, 0, w1T + (long)l*DMLP*NDIM, NDIM, 0, 0,
            nullptr, m, nullptr, DMLP, 0, 0, b1 + l*DMLP, nullptr, 1.f, NDIM, 1);
        // MLP2 (192 CTAs)
        mma_gemm<64,64,1,2><<<dim3(NDIM/64, MALL/64, 1), 256, S_64_64>>>(
            m, DMLP, 0, 0, w2T + (long)l*NDIM*DMLP, DMLP, 0, 0,
            x, nullptr, nullptr, NDIM, 0, 0, b2 + l*NDIM, nullptr, 1.f, DMLP, 1);
    }

    ln_kernel<0><<<MALL, 256>>>(x, lnf_w, lnf_b, out, nullptr);
}

// round 16
// speedup vs baseline: 1.0917x; 1.0244x over previous
#include <cuda_runtime.h>
#include <cuda_fp16.h>
#include <cstdint>
#include <math.h>

#define NDIM 768
#define NTOK 512
#define BSZ 2
#define MALL 1024
#define NHEADS 12
#define DHEAD 64
#define DMLP 3072
#define NDEPTH 4
#define QKVW 2304
#define PATCHES 512
#define NBH (BSZ*NHEADS)

__device__ __forceinline__ uint32_t smem_u32(const void* p){
    uint32_t a;
    asm("{ .reg .u64 t; cvta.to.shared.u64 t, %1; cvt.u32.u64 %0, t; }" : "=r"(a) : "l"(p));
    return a;
}
#define CPA16(d, s) asm volatile("cp.async.cg.shared.global [%0], [%1], 16;" :: "r"(d), "l"(s))
#define CP_COMMIT() asm volatile("cp.async.commit_group;" ::: "memory")
#define CP_WAIT1()  asm volatile("cp.async.wait_group 1;" ::: "memory")
#define CP_WAIT0()  asm volatile("cp.async.wait_group 0;" ::: "memory")

__device__ __forceinline__ void ldm4(uint32_t addr, uint32_t* r){
    asm volatile("ldmatrix.sync.aligned.m8n8.x4.shared.b16 {%0,%1,%2,%3}, [%4];"
        : "=r"(r[0]), "=r"(r[1]), "=r"(r[2]), "=r"(r[3]) : "r"(addr));
}
__device__ __forceinline__ void mma16816(float* c, const uint32_t* a, const uint32_t* b){
    asm volatile("mma.sync.aligned.m16n8k16.row.col.f32.f16.f16.f32 "
        "{%0,%1,%2,%3}, {%4,%5,%6,%7}, {%8,%9}, {%0,%1,%2,%3};"
        : "+f"(c[0]), "+f"(c[1]), "+f"(c[2]), "+f"(c[3])
        : "r"(a[0]), "r"(a[1]), "r"(a[2]), "r"(a[3]), "r"(b[0]), "r"(b[1]));
}

// ---------------- scratch ----------------
__device__ __align__(256) __half g_pat[MALL*PATCHES];
__device__ __align__(256) __half g_cw[NDIM*PATCHES];
__device__ __align__(256) __half g_wqkvT[NDEPTH*QKVW*NDIM];
__device__ __align__(256) __half g_woT[NDEPTH*NDIM*NDIM];
__device__ __align__(256) __half g_w1T[NDEPTH*DMLP*NDIM];
__device__ __align__(256) __half g_w2T[NDEPTH*NDIM*DMLP];
__device__ __align__(256) float  g_x[MALL*NDIM];
__device__ __align__(256) __half g_h[MALL*NDIM];
__device__ __align__(256) __half g_qkv[MALL*QKVW];
__device__ __align__(256) __half g_p[NBH*NTOK*NTOK];
__device__ __align__(256) __half g_vt[NBH*DHEAD*NTOK];
__device__ __align__(256) __half g_o[MALL*NDIM];
__device__ __align__(256) __half g_m[MALL*DMLP];

// ---------------- prep kernels ----------------
__global__ void im2col_half(const float* __restrict__ vol, __half* __restrict__ o){
    int idx = blockIdx.x * 256 + threadIdx.x;
    int m = idx & 511, tkn = idx >> 9, n = tkn & 511, b = tkn >> 9;
    int k = m & 7, j = (m >> 3) & 7, i = m >> 6;
    int pw = n & 7, ph = (n >> 3) & 7, pd = n >> 6;
    o[idx] = __float2half_rn(vol[((long)b << 18) + (pd*8+i)*4096 + (ph*8+j)*64 + (pw*8+k)]);
}
__global__ void conv_half(const float* __restrict__ in, __half* __restrict__ o, int n){
    int idx = blockIdx.x * 256 + threadIdx.x;
    if (idx >= n) return;
    o[idx] = __float2half_rn(in[idx]);
}
// transpose+convert: fp32 [L][R][C] -> fp16 [L][C][R], 64R x 32C tiles
__global__ void wt_half(const float* __restrict__ in, __half* __restrict__ o, int R, int C){
    __shared__ float tf[64][33];
    int z = blockIdx.z;
    const float* ip = in + (long)z * R * C;
    int r0 = blockIdx.y * 64, c0 = blockIdx.x * 32;
    int tx = threadIdx.x, ty = threadIdx.y;   // 32 x 8
#pragma unroll
    for (int i = 0; i < 8; i++)
        tf[ty + 8*i][tx] = ip[(long)(r0 + ty + 8*i) * C + c0 + tx];
    __syncthreads();
    long ob = (long)z * R * C;
#pragma unroll
    for (int i = 0; i < 4; i++) {
        int c = ty + 8*i;
        int r = tx * 2;
        __half2 v = __halves2half2(__float2half_rn(tf[r][c]),
                                   __float2half_rn(tf[r+1][c]));
        *reinterpret_cast<__half2*>(&o[ob + (long)(c0 + c) * R + r0 + r]) = v;
    }
}

// ---------------- LN: 192 thr/row, float4 loads, fp16 or fp32 out ----------------
template <int HALF>
__global__ void __launch_bounds__(192) ln_kernel(
    const float* __restrict__ x, const float* __restrict__ w,
    const float* __restrict__ bb, float* __restrict__ of,
    __half* __restrict__ oh){
    __shared__ float red1[6], red2[6];
    const int row = blockIdx.x, t = threadIdx.x;
    const int lane = t & 31, warp = t >> 5;
    float4 xv = *reinterpret_cast<const float4*>(x + (long)row*NDIM + t*4);
    float s1 = xv.x + xv.y + xv.z + xv.w;
    float s2 = xv.x*xv.x + xv.y*xv.y + xv.z*xv.z + xv.w*xv.w;
#pragma unroll
    for (int o = 16; o; o >>= 1) {
        s1 += __shfl_xor_sync(~0u, s1, o);
        s2 += __shfl_xor_sync(~0u, s2, o);
    }
    if (lane == 0) { red1[warp] = s1; red2[warp] = s2; }
    __syncthreads();
    if (t < 32) {
        float r1 = (t < 6) ? red1[t] : 0.0f;
        float r2 = (t < 6) ? red2[t] : 0.0f;
#pragma unroll
        for (int o = 4; o; o >>= 1) {
            r1 += __shfl_xor_sync(~0u, r1, o);
            r2 += __shfl_xor_sync(~0u, r2, o);
        }
        if (t == 0) { red1[0] = r1; red2[0] = r2; }
    }
    __syncthreads();
    float mean = red1[0] * (1.0f / NDIM);
    float var  = red2[0] * (1.0f / NDIM) - mean * mean;
    float rs = rsqrtf(var + 1e-5f);
    float4 wv = *reinterpret_cast<const float4*>(w + t*4);
    float4 bv = *reinterpret_cast<const float4*>(bb + t*4);
    float y0 = (xv.x-mean)*rs*wv.x + bv.x;
    float y1 = (xv.y-mean)*rs*wv.y + bv.y;
    float y2 = (xv.z-mean)*rs*wv.z + bv.z;
    float y3 = (xv.w-mean)*rs*wv.w + bv.w;
    if (HALF) {
        __half2* op = reinterpret_cast<__half2*>(oh + (long)row*NDIM + t*4);
        op[0] = __halves2half2(__float2half_rn(y0), __float2half_rn(y1));
        op[1] = __halves2half2(__float2half_rn(y2), __float2half_rn(y3));
    } else {
        *reinterpret_cast<float4*>(of + (long)row*NDIM + t*4) = make_float4(y0, y1, y2, y3);
    }
}

// ---------------- softmax: warp-per-row, in-place fp16, no barriers ----------------
__global__ void __launch_bounds__(256) softmax_half(__half* __restrict__ ph){
    const int lane = threadIdx.x & 31, warp = threadIdx.x >> 5;
    const long row = (long)blockIdx.x * 8 + warp;
    __half* pr = ph + row * NTOK + lane * 16;
    uint4 u0 = *reinterpret_cast<const uint4*>(pr);
    uint4 u1 = *reinterpret_cast<const uint4*>(pr + 8);
    float v[16];
    {
        const uint32_t uu[8] = {u0.x,u0.y,u0.z,u0.w,u1.x,u1.y,u1.z,u1.w};
#pragma unroll
        for (int i = 0; i < 8; i++) {
            float2 f = __half22float2(*reinterpret_cast<const __half2*>(&uu[i]));
            v[i*2] = f.x; v[i*2+1] = f.y;
        }
    }
    float m = v[0];
#pragma unroll
    for (int i = 1; i < 16; i++) m = fmaxf(m, v[i]);
#pragma unroll
    for (int o = 16; o; o >>= 1) m = fmaxf(m, __shfl_xor_sync(~0u, m, o));
    float s = 0.0f;
#pragma unroll
    for (int i = 0; i < 16; i++) { v[i] = __expf(v[i] - m); s += v[i]; }
#pragma unroll
    for (int o = 16; o; o >>= 1) s += __shfl_xor_sync(~0u, s, o);
    float inv = 1.0f / s;
    uint32_t out[8];
#pragma unroll
    for (int i = 0; i < 8; i++) {
        __half2 h = __halves2half2(__float2half_rn(v[i*2]*inv),
                                   __float2half_rn(v[i*2+1]*inv));
        out[i] = *reinterpret_cast<uint32_t*>(&h);
    }
    *reinterpret_cast<uint4*>(pr)     = make_uint4(out[0], out[1], out[2], out[3]);
    *reinterpret_cast<uint4*>(pr + 8) = make_uint4(out[4], out[5], out[6], out[7]);
}

// ---------------- pure-fp16 GEMM via mma.sync ----------------
// C[M,N] = A[M,K] @ B[N,K]^T. 3-stage cp.async ring.
// EPI: 0 fp16 acc*scale | 1 fp32 residual+=acc+bias | 2 tanh(acc+bias)->fp16
//      3 acc+bias+pos->fp32 | 4 acc->fp16 | 5 qkv fused (Q,K rows; V->vt transposed)
template <int BM, int BN>
__device__ __forceinline__ void ld_stage(uint32_t sb, int tid,
    const __half* pA, const __half* pB,
    long long lda, long long ldb, int row0, int col0, int k0){
    constexpr int ASZ = BM*80;
#pragma unroll
    for (int i = 0; i < BM/64; i++) {
        int ch = tid + i*256;
        int r = ch >> 2, c = ch & 3;
        uint32_t so = r*80 + c*16;
        CPA16(sb + so, pA + (long long)(row0 + r) * lda + k0 + c*8);
    }
#pragma unroll
    for (int i = 0; i < BN/64; i++) {
        int ch = tid + i*256;
        int r = ch >> 2, c = ch & 3;
        uint32_t so = r*80 + c*16;
        CPA16(sb + ASZ + so, pB + (long long)(col0 + r) * ldb + k0 + c*8);
    }
}

template <int BM, int BN, int EPI, int OCC>
__global__ void __launch_bounds__(256, OCC) mma_gemm(
    const __half* __restrict__ A, long long lda, long long aSB, long long aSH,
    const __half* __restrict__ B, long long ldb, long long bSB, long long bSH,
    float* __restrict__ Cf, __half* __restrict__ Oh, __half* __restrict__ Vt,
    long long ldc, long long cSB, long long cSH,
    const float* __restrict__ bias, const float* __restrict__ pos,
    float scale, int K, int heads)
{
    extern __shared__ __align__(128) char smem_raw[];
    uint32_t sb = smem_u32(smem_raw);
    constexpr int ASZ = BM*80;
    constexpr int BUF = (BM+BN)*80;
    constexpr int MW = BM/32;
    constexpr int NW = 8/MW;
    constexpr int WN = BN/NW;
    constexpr int NP = WN/16;
    constexpr int NT = WN/8;

    const int tid = threadIdx.x, lane = tid & 31, warp = tid >> 5;
    const int warpM = warp % MW, warpN = warp / MW;
    const int z = blockIdx.z, zb = z / heads, zh = z % heads;
    const __half* pA = A + zb*aSB + zh*aSH;
    const __half* pB = B + zb*bSB + zh*bSH;
    const long long cOff = zb*cSB + zh*cSH;
    const int row0 = blockIdx.y * BM, col0 = blockIdx.x * BN;

    float acc[2][NT][4];
#pragma unroll
    for (int a = 0; a < 2; a++)
#pragma unroll
        for (int b = 0; b < NT; b++)
#pragma unroll
            for (int c = 0; c < 4; c++) acc[a][b][c] = 0.0f;

    const int nst = K >> 5;
    ld_stage<BM,BN>(sb, tid, pA, pB, lda, ldb, row0, col0, 0);
    CP_COMMIT();
    if (nst > 1) {
        ld_stage<BM,BN>(sb + BUF, tid, pA, pB, lda, ldb, row0, col0, 32);
        CP_COMMIT();
    }

    const int L = lane & 7, jj = lane >> 3;
    for (int st = 0; st < nst; st++) {
        if (st < nst - 1) CP_WAIT1(); else CP_WAIT0();
        __syncthreads();
        if (st + 2 < nst) {
            ld_stage<BM,BN>(sb + ((st+2)%3)*BUF, tid, pA, pB,
                            lda, ldb, row0, col0, (st+2)*32);
            CP_COMMIT();
        }
        uint32_t base = sb + (st % 3) * BUF;
#pragma unroll
        for (int ks = 0; ks < 2; ks++) {
            uint32_t a_[2][4];
#pragma unroll
            for (int mi = 0; mi < 2; mi++) {
                int mrow = warpM*32 + mi*16 + (jj & 1)*8 + L;
                int kcol = ks*16 + (jj >> 1)*8;
                ldm4(base + mrow*80 + kcol*2, a_[mi]);
            }
            uint32_t b_[NP][4];
#pragma unroll
            for (int np = 0; np < NP; np++) {
                int nrow = warpN*WN + np*16 + (jj >> 1)*8 + L;
                int kcol = ks*16 + (jj & 1)*8;
                ldm4(base + ASZ + nrow*80 + kcol*2, b_[np]);
            }
#pragma unroll
            for (int mi = 0; mi < 2; mi++)
#pragma unroll
                for (int np = 0; np < NP; np++)
#pragma unroll
                    for (int si = 0; si < 2; si++) {
                        uint32_t f[2] = { b_[np][si*2], b_[np][si*2+1] };
                        mma16816(acc[mi][np*2 + si], a_[mi], f);
                    }
        }
    }

#pragma unroll
    for (int mi = 0; mi < 2; mi++)
#pragma unroll
        for (int nt = 0; nt < NT; nt++) {
            float* c = acc[mi][nt];
            int col = col0 + warpN*WN + nt*8 + (lane & 3)*2;
#pragma unroll
            for (int hf = 0; hf < 2; hf++) {
                int row = row0 + warpM*32 + mi*16 + (lane >> 2) + hf*8;
                float v0 = c[hf*2 + 0], v1 = c[hf*2 + 1];
                if (EPI == 0) {
                    long long off = cOff + (long long)row*ldc + col;
                    *reinterpret_cast<__half2*>(Oh + off) =
                        __halves2half2(__float2half_rn(v0*scale), __float2half_rn(v1*scale));
                } else if (EPI == 1) {
                    float2* cp = reinterpret_cast<float2*>(Cf + cOff + (long long)row*ldc + col);
                    float2 old = *cp;
                    *cp = make_float2(old.x + v0 + bias[col], old.y + v1 + bias[col+1]);
                } else if (EPI == 3) {
                    const float2* pp = reinterpret_cast<const float2*>(
                        pos + (long long)(row & (NTOK-1))*ldc + col);
                    float2 pv = *pp;
                    float2* cp = reinterpret_cast<float2*>(Cf + (long long)row*ldc + col);
                    *cp = make_float2(v0 + bias[col] + pv.x, v1 + bias[col+1] + pv.y);
                } else if (EPI == 5) {
                    if (col0 < 2*NDIM) {
                        long long off = (long long)row*ldc + col;
                        *reinterpret_cast<__half2*>(Oh + off) =
                            __halves2half2(__float2half_rn(v0), __float2half_rn(v1));
                    } else {
                        int bb2 = row >> 9, t2 = row & (NTOK-1);
                        int hd = col - 2*NDIM, hh2 = hd >> 6, d = hd & (DHEAD-1);
                        long vtb = ((long)(bb2*NHEADS + hh2)*DHEAD + d)*NTOK + t2;
                        Vt[vtb] = __float2half_rn(v0);
                        Vt[vtb + NTOK] = __float2half_rn(v1);
                    }
                } else {
                    if (EPI == 2) {
                        v0 = tanhf(v0 + bias[col]);
                        v1 = tanhf(v1 + bias[col+1]);
                    }
                    long long off = cOff + (long long)row*ldc + col;
                    *reinterpret_cast<__half2*>(Oh + off) =
                        __halves2half2(__float2half_rn(v0), __float2half_rn(v1));
                }
            }
        }
}

// ---------------- host ----------------
extern "C" void kernel_launch(void* const* d_in, const int* in_sizes, int n_in,
                              void* d_out, int out_size)
{
    const float* volume    = (const float*)d_in[0];
    const float* conv_w    = (const float*)d_in[1];
    const float* conv_b    = (const float*)d_in[2];
    const float* pos_embed = (const float*)d_in[3];
    const float* ln1_w     = (const float*)d_in[4];
    const float* ln1_b     = (const float*)d_in[5];
    const float* w_qkv     = (const float*)d_in[6];
    const float* w_o       = (const float*)d_in[7];
    const float* b_o       = (const float*)d_in[8];
    const float* ln2_w     = (const float*)d_in[9];
    const float* ln2_b     = (const float*)d_in[10];
    const float* w1        = (const float*)d_in[11];
    const float* b1        = (const float*)d_in[12];
    const float* w2        = (const float*)d_in[13];
    const float* b2        = (const float*)d_in[14];
    const float* lnf_w     = (const float*)d_in[15];
    const float* lnf_b     = (const float*)d_in[16];
    float* out = (float*)d_out;

    __half *pat,*cw,*wqT,*woT,*w1T,*w2T,*h,*qkv,*p,*vt,*o,*m;
    float *x;
    cudaGetSymbolAddress((void**)&pat, g_pat);
    cudaGetSymbolAddress((void**)&cw, g_cw);
    cudaGetSymbolAddress((void**)&wqT, g_wqkvT);
    cudaGetSymbolAddress((void**)&woT, g_woT);
    cudaGetSymbolAddress((void**)&w1T, g_w1T);
    cudaGetSymbolAddress((void**)&w2T, g_w2T);
    cudaGetSymbolAddress((void**)&x, g_x);
    cudaGetSymbolAddress((void**)&h, g_h);
    cudaGetSymbolAddress((void**)&qkv, g_qkv);
    cudaGetSymbolAddress((void**)&p, g_p);
    cudaGetSymbolAddress((void**)&vt, g_vt);
    cudaGetSymbolAddress((void**)&o, g_o);
    cudaGetSymbolAddress((void**)&m, g_m);

    const int S_128_128 = 3*(128+128)*80;   // 61440
    const int S_128_192 = 3*(128+192)*80;   // 76800
    const int S_64_64   = 3*(64+64)*80;     // 30720
    cudaFuncSetAttribute((const void*)mma_gemm<128,128,5,2>, cudaFuncAttributeMaxDynamicSharedMemorySize, S_128_128);
    cudaFuncSetAttribute((const void*)mma_gemm<128,128,0,2>, cudaFuncAttributeMaxDynamicSharedMemorySize, S_128_128);
    cudaFuncSetAttribute((const void*)mma_gemm<64,64,4,2>,   cudaFuncAttributeMaxDynamicSharedMemorySize, S_64_64);
    cudaFuncSetAttribute((const void*)mma_gemm<64,64,1,2>,   cudaFuncAttributeMaxDynamicSharedMemorySize, S_64_64);
    cudaFuncSetAttribute((const void*)mma_gemm<64,64,3,2>,   cudaFuncAttributeMaxDynamicSharedMemorySize, S_64_64);
    cudaFuncSetAttribute((const void*)mma_gemm<128,192,2,2>, cudaFuncAttributeMaxDynamicSharedMemorySize, S_128_192);

    dim3 tb(32, 8);

    im2col_half<<<(MALL*PATCHES)/256, 256>>>(volume, pat);
    conv_half<<<(NDIM*PATCHES)/256, 256>>>(conv_w, cw, NDIM*PATCHES);
    wt_half<<<dim3(QKVW/32, NDIM/64, NDEPTH), tb>>>(w_qkv, wqT, NDIM, QKVW);
    wt_half<<<dim3(NDIM/32, NDIM/64, NDEPTH), tb>>>(w_o, woT, NDIM, NDIM);
    wt_half<<<dim3(DMLP/32, NDIM/64, NDEPTH), tb>>>(w1, w1T, NDIM, DMLP);
    wt_half<<<dim3(NDIM/32, DMLP/64, NDEPTH), tb>>>(w2, w2T, DMLP, NDIM);

    // patch embed: x = patches @ conv_w^T + conv_b + pos  (192 CTAs)
    mma_gemm<64,64,3,2><<<dim3(NDIM/64, MALL/64, 1), 256, S_64_64>>>(
        pat, PATCHES, 0, 0, cw, PATCHES, 0, 0,
        x, nullptr, nullptr, NDIM, 0, 0, conv_b, pos_embed, 1.f, PATCHES, 1);

    for (int l = 0; l < NDEPTH; ++l) {
        ln_kernel<1><<<MALL, 192>>>(x, ln1_w + l*NDIM, ln1_b + l*NDIM, nullptr, h);
        // QKV fused: Q,K rows stored; V transposed into vt
        mma_gemm<128,128,5,2><<<dim3(QKVW/128, MALL/128, 1), 256, S_128_128>>>(
            h, NDIM, 0, 0, wqT + (long)l*QKVW*NDIM, NDIM, 0, 0,
            nullptr, qkv, vt, QKVW, 0, 0, nullptr, nullptr, 1.f, NDIM, 1);
        // QK -> fp16 scores directly into p
        mma_gemm<128,128,0,2><<<dim3(NTOK/128, NTOK/128, NBH), 256, S_128_128>>>(
            qkv, QKVW, (long long)NTOK*QKVW, DHEAD,
            qkv + NDIM, QKVW, (long long)NTOK*QKVW, DHEAD,
            nullptr, p, nullptr, NTOK, (long long)NHEADS*NTOK*NTOK, (long long)NTOK*NTOK,
            nullptr, nullptr, 0.125f, DHEAD, NHEADS);
        // softmax in-place on p (warp per row)
        softmax_half<<<NBH*NTOK/8, 256>>>(p);
        // PV (192 CTAs)
        mma_gemm<64,64,4,2><<<dim3(1, NTOK/64, NBH), 256, S_64_64>>>(
            p, NTOK, (long long)NHEADS*NTOK*NTOK, (long long)NTOK*NTOK,
            vt, NTOK, (long long)NHEADS*DHEAD*NTOK, (long long)DHEAD*NTOK,
            nullptr, o, nullptr, NDIM, (long long)NTOK*NDIM, DHEAD,
            nullptr, nullptr, 1.f, NTOK, NHEADS);
        // O-proj (192 CTAs)
        mma_gemm<64,64,1,2><<<dim3(NDIM/64, MALL/64, 1), 256, S_64_64>>>(
            o, NDIM, 0, 0, woT + (long)l*NDIM*NDIM, NDIM, 0, 0,
            x, nullptr, nullptr, NDIM, 0, 0, b_o + l*NDIM, nullptr, 1.f, NDIM, 1);
        ln_kernel<1><<<MALL, 192>>>(x, ln2_w + l*NDIM, ln2_b + l*NDIM, nullptr, h);
        // MLP1 (128x192)
        mma_gemm<128,192,2,2><<<dim3(DMLP/192, MALL/128, 1), 256, S_128_192>>>(
            h, NDIM, 0, 0, w1T + (long)l*DMLP*NDIM, NDIM, 0, 0,
            nullptr, m, nullptr, DMLP, 0, 0, b1 + l*DMLP, nullptr, 1.f, NDIM, 1);
        // MLP2 (192 CTAs)
        mma_gemm<64,64,1,2><<<dim3(NDIM/64, MALL/64, 1), 256, S_64_64>>>(
            m, DMLP, 0, 0, w2T + (long)l*NDIM*DMLP, DMLP, 0, 0,
            x, nullptr, nullptr, NDIM, 0, 0, b2 + l*NDIM, nullptr, 1.f, DMLP, 1);
    }

    ln_kernel<0><<<MALL, 192>>>(x, lnf_w, lnf_b, out, nullptr);
}